// round 16
// baseline (speedup 1.0000x reference)
#include <cuda_runtime.h>

#define BB 64
#define NN 4096
#define DD 129
#define EPSV 1e-7f
#define SUBS 16         // blocks per batch
#define BPW 32          // batches per wave
#define PTSB 256        // points per block per wave
#define NW 8            // warps per block

__device__ float g_spart[BB * SUBS * DD];
__device__ float g_varpart[BB * SUBS];
__device__ unsigned int g_cnt1[BB];   // monotonic epoch counters (never reset)
__device__ unsigned int g_cnt2[BB];

// Warp-level block reduce: 2 block barriers. Result in all threads.
__device__ __forceinline__ float block_reduce_w(float v, float* s8, int w, int l) {
#pragma unroll
    for (int o = 16; o > 0; o >>= 1) v += __shfl_xor_sync(0xffffffffu, v, o);
    if (l == 0) s8[w] = v;
    __syncthreads();
    float r = 0.f;
#pragma unroll
    for (int i = 0; i < NW; i++) r += s8[i];
    __syncthreads();
    return r;
}

// Reduce 4 per-lane accumulators across the warp in 6 shuffles.
// Returns: lane l holds the 32-lane total of p[l&3].
__device__ __forceinline__ float reduce4(float p0, float p1, float p2, float p3,
                                         int l) {
    float v01 = (l & 1) ? p1 : p0;
    float o01 = (l & 1) ? p0 : p1;
    v01 += __shfl_xor_sync(0xffffffffu, o01, 1);
    float v23 = (l & 1) ? p3 : p2;
    float o23 = (l & 1) ? p2 : p3;
    v23 += __shfl_xor_sync(0xffffffffu, o23, 1);
    float v = (l & 2) ? v23 : v01;
    float o = (l & 2) ? v01 : v23;
    v += __shfl_xor_sync(0xffffffffu, o, 2);
    v += __shfl_xor_sync(0xffffffffu, v, 4);
    v += __shfl_xor_sync(0xffffffffu, v, 8);
    v += __shfl_xor_sync(0xffffffffu, v, 16);
    return v;
}

__device__ __forceinline__ float fast_acosh(float alpha) {
    return __logf(alpha + sqrtf((alpha - 1.f) * (alpha + 1.f)));
}

// Split epoch barrier (monotonic counters across graph replays).
__device__ __forceinline__ unsigned int epoch_arrive(unsigned int* cnt) {
    unsigned int ticket = atomicAdd(cnt, 1u);
    return (ticket / SUBS + 1u) * SUBS;
}
__device__ __forceinline__ void epoch_wait(unsigned int* cnt, unsigned int target) {
    while (atomicAdd(cnt, 0u) < target) __nanosleep(32);
    __threadfence();
}

// ---- Phase 1: raw sum over 256 points -> spart; beta per point -> sbeta_w ----
__device__ __forceinline__ void phase1(
    const float* __restrict__ xb, const float* sbm,
    float* sbuf, float* sbeta_w, float* __restrict__ spart_dst,
    int w, int l, int tid) {
    float fbm_r[7], fbm_e[4];
#pragma unroll
    for (int i = 0; i < 7; i++) {
        int c = 4 * l - 3 + i;
        fbm_r[i] = (c > 0) ? sbm[c] : ((c == 0) ? -sbm[0] : 0.f);
    }
#pragma unroll
    for (int i = 0; i < 4; i++) fbm_e[i] = sbm[125 + i];

    for (int i = l; i < DD; i += 32) sbuf[w * DD + i] = 0.f;
    __syncwarp();
    float acc_r[7] = {0, 0, 0, 0, 0, 0, 0};
    float acc_e[4] = {0, 0, 0, 0};
#pragma unroll
    for (int m = 0; m < 8; m++) {
        int g = w + NW * m;
        const float4* p4 = (const float4*)(xb + (size_t)g * 4 * DD);
        float4 v[4];
#pragma unroll
        for (int k = 0; k < 4; k++) v[k] = p4[l + 32 * k];
        float4 ve = p4[128];
        float pb[4] = {0, 0, 0, 0};
#pragma unroll
        for (int k = 0; k < 4; k++) {
            float xr0[4] = {v[k].x, v[k].y, v[k].z, v[k].w};
#pragma unroll
            for (int j = 0; j < 4; j++) {
                float xv = xr0[j];
                if (l == 0 && j < k) {
                    int i = 4 - k + j;
                    acc_e[i] += xv;
                    pb[k - 1] += fbm_e[i] * xv;
                } else {
                    int i = j - k + 3;
                    acc_r[i] += xv;
                    pb[k] += fbm_r[i] * xv;
                }
            }
        }
        if (l == 0) {
            acc_e[0] += ve.x; acc_e[1] += ve.y;
            acc_e[2] += ve.z; acc_e[3] += ve.w;
            pb[3] += fbm_e[0] * ve.x + fbm_e[1] * ve.y +
                     fbm_e[2] * ve.z + fbm_e[3] * ve.w;
        }
        float pbv = reduce4(pb[0], pb[1], pb[2], pb[3], l);
        if (l < 4) sbeta_w[4 * g + l] = pbv;
    }
#pragma unroll
    for (int i = 0; i < 7; i++) {
        int c = 4 * l - 3 + i;
        if (c >= 0) sbuf[w * DD + c] += acc_r[i];
        __syncwarp();
    }
    if (l == 0) {
#pragma unroll
        for (int i = 0; i < 4; i++) sbuf[w * DD + 125 + i] += acc_e[i];
    }
    __syncthreads();
    if (tid < DD) {
        float s = 0.f;
#pragma unroll
        for (int w2 = 0; w2 < NW; w2++) s += sbuf[w2 * DD + tid];
        spart_dst[tid] = s;
    }
    __threadfence();
    __syncthreads();
}

// ---- mu + per-batch scalars (after barrier 1 of batch b) ----
__device__ __forceinline__ void mu_scalars(
    int b, float* smu_w, float bmr, float bb2, float sgn,
    float* s8, int w, int l, int tid,
    float& lmm, float& lmb, float& lkdi, float& lww) {
    float sv = 0.f;
    if (tid < DD) {
#pragma unroll
        for (int s2 = 0; s2 < SUBS; s2++)
            sv += __ldcg(&g_spart[(b * SUBS + s2) * DD + tid]);
    }
    float r = block_reduce_w(-sgn * sv * sv, s8, w, l);  // -ldot(s,s)
    float inv = rsqrtf(fmaxf(r, EPSV));
    float mv = sv * inv;
    if (tid < DD) smu_w[tid] = mv;
    lmm = block_reduce_w(sgn * mv * mv, s8, w, l);
    lmb = block_reduce_w(sgn * mv * bmr, s8, w, l);
    lkdi = 1.f / (1.f - lmb);
    lww = lmm + 2.f * lmb + bb2;
}

// ---- Phase 2: a per point + coef parts -> s4_w; varpart + arrive2 ----
__device__ __forceinline__ void phase2(
    const float* __restrict__ xb, const float* smu_w,
    float lmm, float lmb, float lkdi, float lww,
    const float* sbeta_w, float4* s4_w, float* s8,
    int b, int sub, int w, int l, int tid, unsigned int& t2a) {
    float fmu_r[7], fmu_e[4];
#pragma unroll
    for (int i = 0; i < 7; i++) {
        int c = 4 * l - 3 + i;
        fmu_r[i] = (c > 0) ? -smu_w[c] : ((c == 0) ? smu_w[0] : 0.f);
    }
#pragma unroll
    for (int i = 0; i < 4; i++) fmu_e[i] = -smu_w[125 + i];

    float vloc = 0.f;
#pragma unroll
    for (int m = 0; m < 8; m++) {
        int g = w + NW * m;
        const float4* p4 = (const float4*)(xb + (size_t)g * 4 * DD);
        float4 v[4];
#pragma unroll
        for (int k = 0; k < 4; k++) v[k] = p4[l + 32 * k];
        float4 ve = p4[128];
        float pa[4] = {0, 0, 0, 0};
#pragma unroll
        for (int k = 0; k < 4; k++) {
            float xr0[4] = {v[k].x, v[k].y, v[k].z, v[k].w};
#pragma unroll
            for (int j = 0; j < 4; j++) {
                float xv = xr0[j];
                if (l == 0 && j < k) pa[k - 1] += fmu_e[4 - k + j] * xv;
                else                 pa[k] += fmu_r[j - k + 3] * xv;
            }
        }
        if (l == 0) {
            pa[3] += fmu_e[0] * ve.x + fmu_e[1] * ve.y +
                     fmu_e[2] * ve.z + fmu_e[3] * ve.w;
        }
        float pav = reduce4(pa[0], pa[1], pa[2], pa[3], l);
        float alpha = fmaxf(pav, 1.f + EPSV);
        float d = fast_acosh(alpha);
        float dd = d * d;
        dd += __shfl_xor_sync(0xffffffffu, dd, 1);
        dd += __shfl_xor_sync(0xffffffffu, dd, 2);
        if (l == 0) vloc += dd;
        float nu2 = 2.f * alpha * pav - alpha * alpha - 1.f;
        float nu = sqrtf(fmaxf(nu2, EPSV));
        float vsr = d / nu;
        float betav = sbeta_w[4 * g + (l & 3)];
        float lbu = betav - alpha * lmb;
        float q = vsr * lbu * lkdi;
        float udot = (-pav - alpha * lmm) + lbu;
        float raw2 = vsr * vsr * nu2 + 2.f * vsr * q * udot + q * q * lww;
        if (l < 4) s4_w[4 * g + l] = make_float4(vsr, q - vsr * alpha, q, raw2);
    }
    if (l == 0) s8[w] = vloc;
    __syncthreads();
    if (tid == 0) {
        float s = 0.f;
#pragma unroll
        for (int w3 = 0; w3 < NW; w3++) s += s8[w3];
        g_varpart[b * SUBS + sub] = s;
        __threadfence();
        t2a = epoch_arrive(&g_cnt2[b]);
    }
}

// ---- Phase 3: sc tail + elementwise stream ----
__device__ __forceinline__ void phase3(
    const float* __restrict__ xb, float* __restrict__ ob,
    const float* smu_w, const float* sbm, const float4* s4_w, float sc,
    int w, int l) {
    float mu_r[7], bm_r[7], mu_e[4], bm_e[4];
#pragma unroll
    for (int i = 0; i < 7; i++) {
        int c = 4 * l - 3 + i;
        mu_r[i] = (c >= 0) ? smu_w[c] : 0.f;
        bm_r[i] = (c >= 0) ? sbm[c] : 0.f;
    }
#pragma unroll
    for (int i = 0; i < 4; i++) { mu_e[i] = smu_w[125 + i]; bm_e[i] = sbm[125 + i]; }

#pragma unroll
    for (int m = 0; m < 8; m++) {
        int g = w + NW * m;
        const float4* p4 = (const float4*)(xb + (size_t)g * 4 * DD);
        float4* o4 = (float4*)(ob + (size_t)g * 4 * DD);

        float4 c4 = s4_w[4 * g + (l & 3)];
        float nn2 = sc * sc * c4.w;
        float nnv = sqrtf(fmaxf(nn2, EPSV));
        float e = __expf(nnv);
        float ei = __expf(-nnv);
        float chv = 0.5f * (e + ei);
        float shnv = 0.5f * (e - ei) / nnv;
        float s3 = shnv * sc;
        float cxv = s3 * c4.x;
        float cmv = s3 * c4.y;
        float cbv = chv + s3 * c4.z;

        float cx[4], cm[4], cb[4];
#pragma unroll
        for (int k = 0; k < 4; k++) {
            cx[k] = __shfl_sync(0xffffffffu, cxv, k);
            cm[k] = __shfl_sync(0xffffffffu, cmv, k);
            cb[k] = __shfl_sync(0xffffffffu, cbv, k);
        }
#pragma unroll
        for (int k = 0; k < 4; k++) {
            float4 v = __ldcs(&p4[l + 32 * k]);
            float xr0[4] = {v.x, v.y, v.z, v.w};
            float orr[4];
#pragma unroll
            for (int j = 0; j < 4; j++) {
                if (l == 0 && j < k) {
                    int i = 4 - k + j, n = k - 1;
                    orr[j] = cx[n] * xr0[j] + cm[n] * mu_e[i] + cb[n] * bm_e[i];
                } else {
                    int i = j - k + 3;
                    orr[j] = cx[k] * xr0[j] + cm[k] * mu_r[i] + cb[k] * bm_r[i];
                }
            }
            __stcs(&o4[l + 32 * k], make_float4(orr[0], orr[1], orr[2], orr[3]));
        }
        if (l == 0) {
            float4 v = __ldcs(&p4[128]);
            float xe0[4] = {v.x, v.y, v.z, v.w};
            float orr[4];
#pragma unroll
            for (int j = 0; j < 4; j++)
                orr[j] = cx[3] * xe0[j] + cm[3] * mu_e[j] + cb[3] * bm_e[j];
            __stcs(&o4[128], make_float4(orr[0], orr[1], orr[2], orr[3]));
        }
    }
}

__global__ __launch_bounds__(256, 4) void fused_kernel(
    const float* __restrict__ x, const float* __restrict__ bias,
    const float* __restrict__ weight, float* __restrict__ out) {
    __shared__ float sbuf[NW * DD];     // phase-1 warp-private staging rows
    __shared__ float s8[NW];            // warp-reduce scratch
    __shared__ float4 s4[2][PTSB];      // per-wave (vs, q-vs*a, q, raw2)
    __shared__ float sbeta[2][PTSB];    // per-wave beta cache
    __shared__ float smu[2][DD];
    __shared__ float sbm[DD];
    __shared__ float sScal[2];

    int tid = threadIdx.x, w = tid >> 5, l = tid & 31;
    int bid = blockIdx.x;
    int sub = bid & (SUBS - 1);
    int bgrp = bid >> 4;   // 0..31
    int b0 = bgrp, b1 = BPW + bgrp;

    const float* xb0 = x + ((size_t)b0 * NN + (size_t)sub * PTSB) * DD;
    const float* xb1 = x + ((size_t)b1 * NN + (size_t)sub * PTSB) * DD;
    float* ob0 = out + ((size_t)b0 * NN + (size_t)sub * PTSB) * DD;
    float* ob1 = out + ((size_t)b1 * NN + (size_t)sub * PTSB) * DD;

    // bias point on manifold
    float bias_v = (tid >= 1 && tid < DD) ? bias[tid - 1] : 0.f;
    float nb2 = block_reduce_w(bias_v * bias_v, s8, w, l);
    float nb = sqrtf(fmaxf(nb2, EPSV));
    float sclb = sinhf(nb) / nb;
    float bmv = (tid == 0) ? coshf(nb) : ((tid < DD) ? sclb * bias_v : 0.f);
    if (tid < DD) sbm[tid] = bmv;
    float sgn = (tid == 0) ? -1.f : 1.f;
    float bmr = (tid < DD) ? bmv : 0.f;
    float bb2 = block_reduce_w(sgn * bmr * bmr, s8, w, l);  // ldot(bm,bm)
    __syncthreads();

    unsigned int t1a0 = 0, t1a1 = 0, t2a0 = 0, t2a1 = 0;

    // ---- P1(w0) + arrive ----
    phase1(xb0, sbm, sbuf, sbeta[0], &g_spart[(b0 * SUBS + sub) * DD], w, l, tid);
    if (tid == 0) t1a0 = epoch_arrive(&g_cnt1[b0]);

    // ---- P1(w1) + arrive (absorbs barrier-1(w0) skew) ----
    phase1(xb1, sbm, sbuf, sbeta[1], &g_spart[(b1 * SUBS + sub) * DD], w, l, tid);
    if (tid == 0) t1a1 = epoch_arrive(&g_cnt1[b1]);

    // ---- wait1(w0), mu(w0), P2(w0) ----
    if (tid == 0) epoch_wait(&g_cnt1[b0], t1a0);
    __syncthreads();
    float lmm0, lmb0, lkdi0, lww0;
    mu_scalars(b0, smu[0], bmr, bb2, sgn, s8, w, l, tid, lmm0, lmb0, lkdi0, lww0);
    phase2(xb0, smu[0], lmm0, lmb0, lkdi0, lww0, sbeta[0], s4[0], s8,
           b0, sub, w, l, tid, t2a0);

    // ---- wait1(w1), mu(w1), P2(w1) (absorbs barrier-2(w0) skew) ----
    if (tid == 0) epoch_wait(&g_cnt1[b1], t1a1);
    __syncthreads();
    float lmm1, lmb1, lkdi1, lww1;
    mu_scalars(b1, smu[1], bmr, bb2, sgn, s8, w, l, tid, lmm1, lmb1, lkdi1, lww1);
    phase2(xb1, smu[1], lmm1, lmb1, lkdi1, lww1, sbeta[1], s4[1], s8,
           b1, sub, w, l, tid, t2a1);

    // ---- wait2(w0), sc(w0), P3(w0) ----
    if (tid == 0) {
        epoch_wait(&g_cnt2[b0], t2a0);
        float vs = 0.f;
#pragma unroll
        for (int s2 = 0; s2 < SUBS; s2++) vs += __ldcg(&g_varpart[b0 * SUBS + s2]);
        sScal[0] = sqrtf(weight[0] / (vs / (float)NN + 1e-6f));
    }
    __syncthreads();
    phase3(xb0, ob0, smu[0], sbm, s4[0], sScal[0], w, l);

    // ---- wait2(w1), sc(w1), P3(w1) (absorbs barrier-2(w1) skew) ----
    if (tid == 0) {
        epoch_wait(&g_cnt2[b1], t2a1);
        float vs = 0.f;
#pragma unroll
        for (int s2 = 0; s2 < SUBS; s2++) vs += __ldcg(&g_varpart[b1 * SUBS + s2]);
        sScal[1] = sqrtf(weight[0] / (vs / (float)NN + 1e-6f));
    }
    __syncthreads();
    phase3(xb1, ob1, smu[1], sbm, s4[1], sScal[1], w, l);
}

extern "C" void kernel_launch(void* const* d_in, const int* in_sizes, int n_in,
                              void* d_out, int out_size) {
    const float* x = (const float*)d_in[0];
    const float* bias = (const float*)d_in[1];
    const float* weight = (const float*)d_in[2];
    float* out = (float*)d_out;

    fused_kernel<<<512, 256>>>(x, bias, weight, out);
}